// round 11
// baseline (speedup 1.0000x reference)
#include <cuda_runtime.h>
#include <cuda_bf16.h>

// ---------------------------------------------------------------------------
// LoongSpikeKernel: K[ch,h,l] = 2*Re( sum_n C_disc[h,n] * exp(dtA[h,n]*l) )
// H=512, NS=64 states/h, L=2048, CH=1.
//
// R11 (on R10's fused single-kernel, single-wave design):
//  - k-loop fully unrolled per chunk (R10 evidence: issue 47% with 8
//    warps/SMSP => branch/scheduling stalls, not throughput).
//  - Packed f32x2 partials stored with STS.64; the lo+hi fold moves to the
//    epilogue (drops MOV+FADD dependent tail from every k).
//  - KCH=16 so ull partial buffer fits 4 CTAs/SM (34KB/CTA).
// ---------------------------------------------------------------------------

#define NS 64   // states per h (M*NST)
#define GS 8    // states per thread
#define NP 4    // packed state-pairs per thread
#define NLANE 32
#define KCH 16  // k-iters buffered in smem per chunk

typedef unsigned long long ull;

// fp32 two-term Cody-Waite reduction + fast sincos.
__device__ __forceinline__ void sincos_cw(float x, float* s, float* c) {
    float k = rintf(x * 0.15915494309189535f);
    float r = fmaf(k, -6.28125f, x);
    r = fmaf(k, -1.9353071795864769e-3f, r);
    __sincosf(r, s, c);
}

__device__ __forceinline__ ull pack2(float lo, float hi) {
    ull r;
    asm("mov.b64 %0, {%1, %2};" : "=l"(r)
        : "r"(__float_as_uint(lo)), "r"(__float_as_uint(hi)));
    return r;
}
__device__ __forceinline__ ull add2(ull a, ull b) {
    ull r; asm("add.rn.f32x2 %0, %1, %2;" : "=l"(r) : "l"(a), "l"(b)); return r;
}
__device__ __forceinline__ ull mul2(ull a, ull b) {
    ull r; asm("mul.rn.f32x2 %0, %1, %2;" : "=l"(r) : "l"(a), "l"(b)); return r;
}
__device__ __forceinline__ ull fma2(ull a, ull b, ull c) {
    ull r; asm("fma.rn.f32x2 %0, %1, %2, %3;" : "=l"(r) : "l"(a), "l"(b), "l"(c)); return r;
}
__device__ __forceinline__ float sum2(ull a) {
    unsigned lo, hi;
    asm("mov.b64 {%0, %1}, %2;" : "=r"(lo), "=r"(hi) : "l"(a));
    return __uint_as_float(lo) + __uint_as_float(hi);
}

// ---------------------------------------------------------------------------
__global__ __launch_bounds__(256, 4) void loong_fused(
    float* __restrict__ out,
    const float* __restrict__ C_real,
    const float* __restrict__ log_dt,
    const float* __restrict__ log_A_real,
    const float* __restrict__ A_imag,
    const float* __restrict__ omega_logit,
    const float* __restrict__ eta_logit,
    int NST, int L) {
    const float OMIN = 1e-6f, OMAX = 100.0f, EMIN = 1e-6f, EMAX = 10.0f;
    const int h    = blockIdx.x;
    const int tid  = threadIdx.x;
    const int g    = tid >> 5;     // state group 0..7 (== warp id)
    const int t    = tid & 31;     // l lane 0..31

    __shared__ float2 s_dtA[NS];
    __shared__ float2 s_C2 [NS];
    __shared__ float4 s_R32[NS];              // (rr, ri, 2*rr, -|r32|^2)
    __shared__ ull    sP[KCH][8][NLANE];      // packed per-k group partials (32 KB)

    // ---- phase 0: per-CTA constants, 64 threads ----
    if (tid < NS) {
        int m = tid / NST;                    // 0..M-1
        int n = tid - m * NST;                // 0..NST-1
        int gi = h * NST + n;

        float dt    = expf(log_dt[h]);
        float omega = OMIN + (OMAX - OMIN) / (1.f + expf(-omega_logit[m]));
        float eta   = EMIN + (EMAX - EMIN) / (1.f + expf(-eta_logit[m]));
        float Are   = -expf(log_A_real[gi]);
        float Aim   = A_imag[gi];
        float Afr   = -omega + eta * Are;
        float Afi   = eta * Aim;
        float Cr    = eta * C_real[gi * 2 + 0];   // CH = 1
        float Ci    = eta * C_real[gi * 2 + 1];
        float dtAr  = Afr * dt;
        float dtAi  = Afi * dt;

        // (exp(dtA) - 1) / (A_frac + 1e-8)
        float er = expf(dtAr);
        float s1, c1; sincos_cw(dtAi, &s1, &c1);
        float nr = er * c1 - 1.f;
        float ni = er * s1;
        float dr  = Afr + 1e-8f, di = Afi;
        float inv = 1.f / (dr * dr + di * di);
        float qr  = (nr * dr + ni * di) * inv;
        float qi  = (ni * dr - nr * di) * inv;
        float Cdr = Cr * qr - Ci * qi;
        float Cdi = Cr * qi + Ci * qr;
        if (sqrtf(Afr * Afr + Afi * Afi) < 1e-6f) { Cdr = Cr * dt; Cdi = Ci * dt; }

        s_dtA[tid] = make_float2(dtAr, dtAi);
        s_C2 [tid] = make_float2(2.f * Cdr, 2.f * Cdi);

        float e32 = expf(32.f * dtAr);
        float s32, c32; sincos_cw(32.f * dtAi, &s32, &c32);
        float rr = e32 * c32, ri = e32 * s32;
        float negq = -expf(64.f * dtAr);
        s_R32[tid] = make_float4(rr, ri, 2.f * rr, negq);
    }
    __syncthreads();

    // ---- phase 1: seed A = s(t), B = s(t+32) for 8 states (4 pairs) ----
    const int base = g * GS;
    ull A[NP], B[NP], twoa[NP], negq[NP];
    const float tf = (float)t;
    const float E = __expf(s_dtA[base].x * tf);   // shared decay across group
#pragma unroll
    for (int p = 0; p < NP; p++) {
        float s0v[2], s1v[2], tw[2], nq[2];
#pragma unroll
        for (int e = 0; e < 2; e++) {
            int i = base + 2 * p + e;
            float2 a = s_dtA[i];
            float2 c = s_C2 [i];
            float4 q = s_R32[i];
            float s, co; sincos_cw(a.y * tf, &s, &co);   // per-state exact phase
            float xr = E * co, xi = E * s;
            float wr = c.x * xr - c.y * xi;      // Re(C2 * e^{dtA t})
            float wi = c.x * xi + c.y * xr;
            s0v[e] = wr;
            s1v[e] = wr * q.x - wi * q.y;        // Re(w * r32)
            tw[e]  = q.z;
            nq[e]  = q.w;
        }
        A[p]    = pack2(s0v[0], s0v[1]);
        B[p]    = pack2(s1v[0], s1v[1]);
        twoa[p] = pack2(tw[0],  tw[1]);
        negq[p] = pack2(nq[0],  nq[1]);
    }

    const int iters = (L + NLANE - 1) / NLANE;    // total k's (64)
    const long long ob = (long long)h * L;

    // ---- phase 2: recurrence ----
    for (int kk0 = 0; kk0 < iters; kk0 += KCH) {
        const int kend = (iters - kk0 < KCH) ? (iters - kk0) : KCH;
        if (kend == KCH) {
            // fully unrolled fast path
#pragma unroll
            for (int k = 0; k < KCH; k += 2) {
                // even: store packed sum(A-pairs), advance A
                sP[k][g][t] = add2(add2(A[0], A[1]), add2(A[2], A[3]));
#pragma unroll
                for (int p = 0; p < NP; p++)
                    A[p] = fma2(B[p], twoa[p], mul2(A[p], negq[p]));
                // odd: store packed sum(B-pairs), advance B
                sP[k + 1][g][t] = add2(add2(B[0], B[1]), add2(B[2], B[3]));
#pragma unroll
                for (int p = 0; p < NP; p++)
                    B[p] = fma2(A[p], twoa[p], mul2(B[p], negq[p]));
            }
        } else {
#pragma unroll 1
            for (int k = 0; k < kend; k += 2) {
                sP[k][g][t] = add2(add2(A[0], A[1]), add2(A[2], A[3]));
#pragma unroll
                for (int p = 0; p < NP; p++)
                    A[p] = fma2(B[p], twoa[p], mul2(A[p], negq[p]));
                sP[k + 1][g][t] = add2(add2(B[0], B[1]), add2(B[2], B[3]));
#pragma unroll
                for (int p = 0; p < NP; p++)
                    B[p] = fma2(A[p], twoa[p], mul2(B[p], negq[p]));
            }
        }
        __syncthreads();
        // epilogue: fold the 8 packed group partials, then lo+hi
        const int lbeg = kk0 * NLANE;
        const int lend = lbeg + kend * NLANE;
        for (int l = lbeg + tid; l < lend && l < L; l += 256) {
            int kk = (l >> 5) - kk0, tt = l & 31;
            ull s = add2(add2(add2(sP[kk][0][tt], sP[kk][1][tt]),
                              add2(sP[kk][2][tt], sP[kk][3][tt])),
                         add2(add2(sP[kk][4][tt], sP[kk][5][tt]),
                              add2(sP[kk][6][tt], sP[kk][7][tt])));
            out[ob + l] = sum2(s);
        }
        __syncthreads();
    }
}

// ---------------------------------------------------------------------------
extern "C" void kernel_launch(void* const* d_in, const int* in_sizes, int n_in,
                              void* d_out, int out_size) {
    const float* C_real      = (const float*)d_in[0];
    const float* log_dt      = (const float*)d_in[1];
    const float* log_A_real  = (const float*)d_in[2];
    const float* A_imag      = (const float*)d_in[3];
    const float* omega_logit = (const float*)d_in[4];
    const float* eta_logit   = (const float*)d_in[5];

    int H   = in_sizes[1];               // 512
    int NST = in_sizes[2] / H;           // 32
    int L   = out_size / H;              // 2048 (CH = 1)

    loong_fused<<<H, 256>>>((float*)d_out, C_real, log_dt, log_A_real,
                            A_imag, omega_logit, eta_logit, NST, L);
}